// round 2
// baseline (speedup 1.0000x reference)
#include <cuda_runtime.h>
#include <math.h>

// ---------------------------------------------------------------------------
// Transformer forward: B=4, S=1024, D=1024, H=8 (full-D heads), V=32000, L=2
// fp32 baseline: tiled SGEMM (128x128x16) + fused softmax/LN.
// All scratch in device globals.
// ---------------------------------------------------------------------------

#define TOK   4096          // B*S
#define DM    1024          // d_model
#define NH    8
#define SEQ   1024
#define BB    4
#define VOC   32000
#define NLAY  2
#define BIG   (1<<30)

// Scratch (module-load allocated; no runtime allocation)
__device__ float g_h   [TOK * DM];             // hidden state        16 MB
__device__ float g_Q   [NH * TOK * DM];        // [h][b*S+s][e]      128 MB
__device__ float g_Kb  [NH * TOK * DM];        //                    128 MB
__device__ float g_Vb  [NH * TOK * DM];        //                    128 MB
__device__ float g_P   [NH * BB * SEQ * SEQ];  // scores/probs       128 MB
__device__ float g_O   [TOK * NH * DM];        // concat heads       128 MB
__device__ float g_a   [TOK * DM];             // attn-out / ffn-out  16 MB
__device__ float g_ffin[TOK * DM];             // ln1 output          16 MB
__device__ float g_mid [TOK * 4 * DM];         // ffn hidden          64 MB

// ---------------------------------------------------------------------------
// Embedding + positional encoding (double precision PE to match numpy float64)
// ---------------------------------------------------------------------------
__global__ void embed_kernel(const int* __restrict__ x,
                             const float* __restrict__ emb,
                             float* __restrict__ out) {
    long idx = (long)blockIdx.x * blockDim.x + threadIdx.x;  // over TOK*DM
    int d = (int)(idx & (DM - 1));
    int t = (int)(idx >> 10);
    int s = t & (SEQ - 1);
    int tok = x[t];
    int i = d >> 1;
    double ang = (double)s / pow(10000.0, (2.0 * (double)i) / (double)DM);
    double pe = (d & 1) ? cos(ang) : sin(ang);
    out[idx] = emb[(long)tok * DM + d] + (float)pe;
}

// ---------------------------------------------------------------------------
// Generic batched SGEMM: C = A * B (+bias) (optional ReLU)
// A: [M,K] row-major (lda), B: NN -> [K,N] (ldb) | NT -> [N,K] (ldb)
// Per-z pointer offset: p += (z/div)*so + (z%div)*si
// Tile 128x128, BK=16, 256 threads, 8x8 per thread. All dims divide evenly.
// ---------------------------------------------------------------------------
template <bool TRANSB, bool RELU>
__global__ __launch_bounds__(256)
void sgemm_kernel(const float* __restrict__ A, const float* __restrict__ B,
                  const float* __restrict__ bias, float* __restrict__ C,
                  int K, int lda, int ldb, int ldc,
                  long Aso, long Asi, int Adiv,
                  long Bso, long Bsi, int Bdiv,
                  long Cso, long Csi, int Cdiv,
                  long bso, long bsi, int bdiv) {
    int z = blockIdx.z;
    A += (long)(z / Adiv) * Aso + (long)(z % Adiv) * Asi;
    B += (long)(z / Bdiv) * Bso + (long)(z % Bdiv) * Bsi;
    C += (long)(z / Cdiv) * Cso + (long)(z % Cdiv) * Csi;
    if (bias) bias += (long)(z / bdiv) * bso + (long)(z % bdiv) * bsi;

    __shared__ float As[16][128];
    __shared__ float Bs[16][128];

    int tid = threadIdx.x;
    int m0 = blockIdx.y * 128;
    int n0 = blockIdx.x * 128;

    float acc[8][8];
#pragma unroll
    for (int i = 0; i < 8; i++)
#pragma unroll
        for (int j = 0; j < 8; j++) acc[i][j] = 0.f;

    int tm = (tid >> 4) * 8;     // 0..120
    int tn = (tid & 15) * 8;     // 0..120

    // A loader: row = tid/2 (0..127), 8 consecutive k at (tid&1)*8
    int arow = tid >> 1;
    int acol = (tid & 1) * 8;
    const float* Ap = A + (long)(m0 + arow) * lda + acol;

    for (int k0 = 0; k0 < K; k0 += 16) {
#pragma unroll
        for (int h = 0; h < 2; h++) {
            float4 av = *(const float4*)(Ap + k0 + h * 4);
            As[acol + h * 4 + 0][arow] = av.x;
            As[acol + h * 4 + 1][arow] = av.y;
            As[acol + h * 4 + 2][arow] = av.z;
            As[acol + h * 4 + 3][arow] = av.w;
        }

        if (!TRANSB) {
            int brr = tid >> 4;            // 0..15 (k)
            int bc = (tid & 15) * 8;       // 0..120 (n)
            float4 bv0 = *(const float4*)(B + (long)(k0 + brr) * ldb + n0 + bc);
            float4 bv1 = *(const float4*)(B + (long)(k0 + brr) * ldb + n0 + bc + 4);
            *(float4*)&Bs[brr][bc] = bv0;
            *(float4*)&Bs[brr][bc + 4] = bv1;
        } else {
            int bn = tid >> 1;             // 0..127 (n)
            int bk = (tid & 1) * 8;        // 0 or 8 (k)
#pragma unroll
            for (int h = 0; h < 2; h++) {
                float4 bv = *(const float4*)(B + (long)(n0 + bn) * ldb + k0 + bk + h * 4);
                Bs[bk + h * 4 + 0][bn] = bv.x;
                Bs[bk + h * 4 + 1][bn] = bv.y;
                Bs[bk + h * 4 + 2][bn] = bv.z;
                Bs[bk + h * 4 + 3][bn] = bv.w;
            }
        }
        __syncthreads();

#pragma unroll
        for (int kk = 0; kk < 16; kk++) {
            float a[8], b[8];
            *(float4*)(a)     = *(float4*)&As[kk][tm];
            *(float4*)(a + 4) = *(float4*)&As[kk][tm + 4];
            *(float4*)(b)     = *(float4*)&Bs[kk][tn];
            *(float4*)(b + 4) = *(float4*)&Bs[kk][tn + 4];
#pragma unroll
            for (int i = 0; i < 8; i++)
#pragma unroll
                for (int j = 0; j < 8; j++) acc[i][j] += a[i] * b[j];
        }
        __syncthreads();
    }

    // Epilogue: bias + relu + store
#pragma unroll
    for (int i = 0; i < 8; i++) {
        long row = m0 + tm + i;
#pragma unroll
        for (int j = 0; j < 8; j += 4) {
            float4 v;
            v.x = acc[i][j + 0];
            v.y = acc[i][j + 1];
            v.z = acc[i][j + 2];
            v.w = acc[i][j + 3];
            if (bias) {
                v.x += bias[n0 + tn + j + 0];
                v.y += bias[n0 + tn + j + 1];
                v.z += bias[n0 + tn + j + 2];
                v.w += bias[n0 + tn + j + 3];
            }
            if (RELU) {
                v.x = fmaxf(v.x, 0.f);
                v.y = fmaxf(v.y, 0.f);
                v.z = fmaxf(v.z, 0.f);
                v.w = fmaxf(v.w, 0.f);
            }
            *(float4*)(C + row * ldc + n0 + tn + j) = v;
        }
    }
}

// ---------------------------------------------------------------------------
// Causal softmax over rows of P: row layout [z=h*4+b][q][k], applies 1/sqrt(D)
// scale and the -1e9 mask for k > q, then softmax. One block per row.
// ---------------------------------------------------------------------------
__global__ void softmax_kernel(float* __restrict__ P) {
    int row = blockIdx.x;
    int q = row & (SEQ - 1);
    float* p = P + (long)row * SEQ;
    int tid = threadIdx.x;       // 256 threads, 4 elems each
    int k0 = tid * 4;
    const float sc = 0.03125f;   // 1/sqrt(1024)

    float4 v = *(const float4*)(p + k0);
    float a0 = (k0 + 0 <= q) ? v.x * sc : -1e9f;
    float a1 = (k0 + 1 <= q) ? v.y * sc : -1e9f;
    float a2 = (k0 + 2 <= q) ? v.z * sc : -1e9f;
    float a3 = (k0 + 3 <= q) ? v.w * sc : -1e9f;

    __shared__ float red[256];
    float mx = fmaxf(fmaxf(a0, a1), fmaxf(a2, a3));
    red[tid] = mx;
    __syncthreads();
    for (int o = 128; o > 0; o >>= 1) {
        if (tid < o) red[tid] = fmaxf(red[tid], red[tid + o]);
        __syncthreads();
    }
    mx = red[0];
    __syncthreads();

    float e0 = expf(a0 - mx);
    float e1 = expf(a1 - mx);
    float e2 = expf(a2 - mx);
    float e3 = expf(a3 - mx);
    red[tid] = e0 + e1 + e2 + e3;
    __syncthreads();
    for (int o = 128; o > 0; o >>= 1) {
        if (tid < o) red[tid] += red[tid + o];
        __syncthreads();
    }
    float inv = 1.f / red[0];

    float4 o4;
    o4.x = e0 * inv; o4.y = e1 * inv; o4.z = e2 * inv; o4.w = e3 * inv;
    *(float4*)(p + k0) = o4;
}

// ---------------------------------------------------------------------------
// Fused residual + LayerNorm: out = LN(X + Y) * g + b. One block per row.
// ---------------------------------------------------------------------------
__global__ void ln_residual_kernel(const float* __restrict__ X,
                                   const float* __restrict__ Y,
                                   const float* __restrict__ g,
                                   const float* __restrict__ b,
                                   float* __restrict__ out) {
    int row = blockIdx.x;
    int tid = threadIdx.x;       // 256 threads, 4 elems each
    int c = tid * 4;
    float4 xv = *(const float4*)(X + (long)row * DM + c);
    float4 yv = *(const float4*)(Y + (long)row * DM + c);
    float v0 = xv.x + yv.x, v1 = xv.y + yv.y, v2 = xv.z + yv.z, v3 = xv.w + yv.w;

    __shared__ float red[256];
    red[tid] = v0 + v1 + v2 + v3;
    __syncthreads();
    for (int o = 128; o > 0; o >>= 1) {
        if (tid < o) red[tid] += red[tid + o];
        __syncthreads();
    }
    float mu = red[0] * (1.f / DM);
    __syncthreads();

    float d0 = v0 - mu, d1 = v1 - mu, d2 = v2 - mu, d3 = v3 - mu;
    red[tid] = d0 * d0 + d1 * d1 + d2 * d2 + d3 * d3;
    __syncthreads();
    for (int o = 128; o > 0; o >>= 1) {
        if (tid < o) red[tid] += red[tid + o];
        __syncthreads();
    }
    float inv = rsqrtf(red[0] * (1.f / DM) + 1e-5f);

    float4 gv = *(const float4*)(g + c);
    float4 bv = *(const float4*)(b + c);
    float4 o4;
    o4.x = d0 * inv * gv.x + bv.x;
    o4.y = d1 * inv * gv.y + bv.y;
    o4.z = d2 * inv * gv.z + bv.z;
    o4.w = d3 * inv * gv.w + bv.w;
    *(float4*)(out + (long)row * DM + c) = o4;
}

// ---------------------------------------------------------------------------
// Host driver
// ---------------------------------------------------------------------------
extern "C" void kernel_launch(void* const* d_in, const int* in_sizes, int n_in,
                              void* d_out, int out_size) {
    const int*   x    = (const int*)  d_in[0];
    const float* emb  = (const float*)d_in[1];
    const float* wq   = (const float*)d_in[2];
    const float* bq   = (const float*)d_in[3];
    const float* wk   = (const float*)d_in[4];
    const float* bk   = (const float*)d_in[5];
    const float* wv   = (const float*)d_in[6];
    const float* bv   = (const float*)d_in[7];
    const float* wr   = (const float*)d_in[8];
    const float* br   = (const float*)d_in[9];
    const float* ln1g = (const float*)d_in[10];
    const float* ln1b = (const float*)d_in[11];
    const float* w1   = (const float*)d_in[12];
    const float* b1   = (const float*)d_in[13];
    const float* w2   = (const float*)d_in[14];
    const float* b2   = (const float*)d_in[15];
    const float* ln2g = (const float*)d_in[16];
    const float* ln2b = (const float*)d_in[17];
    const float* wf   = (const float*)d_in[18];
    const float* bf   = (const float*)d_in[19];
    float* out = (float*)d_out;

    float *ph, *pQ, *pK, *pV, *pP, *pO, *pa, *pf, *pm;
    cudaGetSymbolAddress((void**)&ph, g_h);
    cudaGetSymbolAddress((void**)&pQ, g_Q);
    cudaGetSymbolAddress((void**)&pK, g_Kb);
    cudaGetSymbolAddress((void**)&pV, g_Vb);
    cudaGetSymbolAddress((void**)&pP, g_P);
    cudaGetSymbolAddress((void**)&pO, g_O);
    cudaGetSymbolAddress((void**)&pa, g_a);
    cudaGetSymbolAddress((void**)&pf, g_ffin);
    cudaGetSymbolAddress((void**)&pm, g_mid);

    // h = emb[x] + posenc
    embed_kernel<<<(TOK * DM) / 256, 256>>>(x, emb, ph);

    for (int l = 0; l < NLAY; l++) {
        const float* wql = wq + (long)l * NH * DM * DM;
        const float* wkl = wk + (long)l * NH * DM * DM;
        const float* wvl = wv + (long)l * NH * DM * DM;
        const float* bql = bq + (long)l * NH * DM;
        const float* bkl = bk + (long)l * NH * DM;
        const float* bvl = bv + (long)l * NH * DM;
        const float* wrl = wr + (long)l * NH * DM * DM;  // [H*D, D]
        const float* brl = br + (long)l * DM;
        const float* w1l = w1 + (long)l * DM * 4 * DM;
        const float* b1l = b1 + (long)l * 4 * DM;
        const float* w2l = w2 + (long)l * 4 * DM * DM;
        const float* b2l = b2 + (long)l * DM;

        // --- Q/K/V projections: per head z -> C[z] = h @ w[z] + bias[z]
        dim3 gqkv(DM / 128, TOK / 128, NH);
        sgemm_kernel<false, false><<<gqkv, 256>>>(ph, wql, bql, pQ,
            DM, DM, DM, DM,
            0, 0, BIG,  0, (long)DM * DM, BIG,  0, (long)TOK * DM, BIG,  0, DM, BIG);
        sgemm_kernel<false, false><<<gqkv, 256>>>(ph, wkl, bkl, pK,
            DM, DM, DM, DM,
            0, 0, BIG,  0, (long)DM * DM, BIG,  0, (long)TOK * DM, BIG,  0, DM, BIG);
        sgemm_kernel<false, false><<<gqkv, 256>>>(ph, wvl, bvl, pV,
            DM, DM, DM, DM,
            0, 0, BIG,  0, (long)DM * DM, BIG,  0, (long)TOK * DM, BIG,  0, DM, BIG);

        // --- scores = Q @ K^T per (h,b): z = h*4+b, each slice contiguous 1024x1024
        dim3 gsc(SEQ / 128, SEQ / 128, NH * BB);
        sgemm_kernel<true, false><<<gsc, 256>>>(pQ, pK, nullptr, pP,
            DM, DM, DM, SEQ,
            0, (long)SEQ * DM, BIG,  0, (long)SEQ * DM, BIG,
            0, (long)SEQ * SEQ, BIG,  0, 0, BIG);

        // --- causal softmax (scale + mask fused)
        softmax_kernel<<<NH * BB * SEQ, 256>>>(pP);

        // --- O = P @ V, written in concat-head layout [tok][h*D+e]
        // C offset: z=h*4+b -> (z/4)*D + (z%4)*(S*H*D)
        sgemm_kernel<false, false><<<gsc, 256>>>(pP, pV, nullptr, pO,
            SEQ, SEQ, DM, NH * DM,
            0, (long)SEQ * SEQ, BIG,  0, (long)SEQ * DM, BIG,
            (long)DM, (long)SEQ * NH * DM, BB,  0, 0, BIG);

        // --- reducing layer: a = O[4096,8192] @ wr[8192,1024] + br
        dim3 gwr(DM / 128, TOK / 128, 1);
        sgemm_kernel<false, false><<<gwr, 256>>>(pO, wrl, brl, pa,
            NH * DM, NH * DM, DM, DM,
            0, 0, BIG,  0, 0, BIG,  0, 0, BIG,  0, 0, BIG);

        // --- ff_in = LN(a + h)
        ln_residual_kernel<<<TOK, 256>>>(pa, ph, ln1g + (long)l * DM,
                                         ln1b + (long)l * DM, pf);

        // --- ffn1: mid = relu(ff_in @ w1 + b1)
        dim3 gf1((4 * DM) / 128, TOK / 128, 1);
        sgemm_kernel<false, true><<<gf1, 256>>>(pf, w1l, b1l, pm,
            DM, DM, 4 * DM, 4 * DM,
            0, 0, BIG,  0, 0, BIG,  0, 0, BIG,  0, 0, BIG);

        // --- ffn2: a = mid @ w2 + b2
        dim3 gf2(DM / 128, TOK / 128, 1);
        sgemm_kernel<false, false><<<gf2, 256>>>(pm, w2l, b2l, pa,
            4 * DM, 4 * DM, DM, DM,
            0, 0, BIG,  0, 0, BIG,  0, 0, BIG,  0, 0, BIG);

        // --- h = LN(ffn_out + ff_in)
        ln_residual_kernel<<<TOK, 256>>>(pa, pf, ln2g + (long)l * DM,
                                         ln2b + (long)l * DM, ph);
    }

    // --- logits = h @ wf + bf
    dim3 gfin(VOC / 128, TOK / 128, 1);
    sgemm_kernel<false, false><<<gfin, 256>>>(ph, wf, bf, out,
        DM, DM, VOC, VOC,
        0, 0, BIG,  0, 0, BIG,  0, 0, BIG,  0, 0, BIG);
}

// round 5
// speedup vs baseline: 2.2215x; 2.2215x over previous
#include <cuda_runtime.h>
#include <cuda_bf16.h>
#include <math.h>
#include <stdint.h>

// ---------------------------------------------------------------------------
// Transformer forward: B=4, S=1024, D=1024, H=8 (full-D heads), V=32000, L=2
// mma.sync (HMMA) bf16 3-product split GEMMs + fused softmax/LN.
// ---------------------------------------------------------------------------

#define TOK   4096
#define DM    1024
#define NH    8
#define SEQ   1024
#define BB    4
#define VOC   32000
#define NLAY  2
#define BIG   (1<<30)

// ----------------------------- scratch -------------------------------------
__device__ float g_h   [TOK * DM];
__device__ float g_Q   [NH * TOK * DM];
__device__ float g_Kb  [NH * TOK * DM];
__device__ float g_Vb  [NH * TOK * DM];
__device__ float g_Vt  [NH * TOK * DM];        // V transposed per (h,b): [e][s]
__device__ float g_P   [NH * BB * SEQ * SEQ];
__device__ float g_O   [TOK * NH * DM];
__device__ float g_a   [TOK * DM];
__device__ float g_ffin[TOK * DM];
__device__ float g_mid [TOK * 4 * DM];
// transposed weights [N,K]
__device__ float g_wqT [NLAY * NH * DM * DM];
__device__ float g_wkT [NLAY * NH * DM * DM];
__device__ float g_wvT [NLAY * NH * DM * DM];
__device__ float g_wrT [NLAY * NH * DM * DM];
__device__ float g_w1T [NLAY * 4 * DM * DM];
__device__ float g_w2T [NLAY * 4 * DM * DM];
__device__ float g_wfT [VOC * DM];

// ----------------------------- helpers -------------------------------------
__device__ __forceinline__ void split2(float v, unsigned short& h, unsigned short& l) {
    __nv_bfloat16 bh = __float2bfloat16(v);
    float r = v - __bfloat162float(bh);
    h = __bfloat16_as_ushort(bh);
    l = __bfloat16_as_ushort(__float2bfloat16(r));
}

__device__ __forceinline__ void mma16816(float* c, const uint32_t* a, const uint32_t* b) {
    asm volatile(
        "mma.sync.aligned.m16n8k16.row.col.f32.bf16.bf16.f32 "
        "{%0,%1,%2,%3}, {%4,%5,%6,%7}, {%8,%9}, {%0,%1,%2,%3};\n"
        : "+f"(c[0]), "+f"(c[1]), "+f"(c[2]), "+f"(c[3])
        : "r"(a[0]), "r"(a[1]), "r"(a[2]), "r"(a[3]), "r"(b[0]), "r"(b[1]));
}

// SMEM tile: 128 rows x 32 bf16, row stride 40 (conflict-free quad loads)
#define TSTRIDE 40
#define TILE_U16 (128 * TSTRIDE)            // 5120 u16 = 10240 B
#define STAGE_U16 (4 * TILE_U16)            // Ahi Alo Bhi Blo
#define GSMEM_BYTES (2 * STAGE_U16 * 2)     // 81920 B

__device__ __forceinline__ uint32_t lds32(const uint16_t* t, int r, int k) {
    return *(const uint32_t*)(t + r * TSTRIDE + k);
}

// ---------------------------------------------------------------------------
// HMMA GEMM: C[M,N] = A[M,K] @ Bg[N,K]^T (+bias) (opt ReLU)
// Tile 128x128x32, 256 thr, warps 2x4 (warp tile 64x32), bf16 3-prod split.
// CAUSAL: 0 none, 1 skip tiles n0 > m0 (scores), 2 K clamp to m0+128 (PV).
// ---------------------------------------------------------------------------
template <int CAUSAL, bool RELU>
__global__ __launch_bounds__(256, 1)
void hgemm(const float* __restrict__ A, const float* __restrict__ B,
           const float* __restrict__ bias, float* __restrict__ C,
           int K, int lda, int ldb, int ldc,
           long Aso, long Asi, int Adiv,
           long Bso, long Bsi, int Bdiv,
           long Cso, long Csi, int Cdiv,
           long bso, long bsi, int bdiv) {
    int m0 = blockIdx.y * 128;
    int n0 = blockIdx.x * 128;
    if (CAUSAL == 1 && n0 > m0) return;        // fully-masked scores tile

    int z = blockIdx.z;
    A += (long)(z / Adiv) * Aso + (long)(z % Adiv) * Asi;
    B += (long)(z / Bdiv) * Bso + (long)(z % Bdiv) * Bsi;
    C += (long)(z / Cdiv) * Cso + (long)(z % Cdiv) * Csi;
    if (bias) bias += (long)(z / bdiv) * bso + (long)(z % bdiv) * bsi;

    extern __shared__ uint16_t sm16[];

    int tid = threadIdx.x;
    int wid = tid >> 5, lane = tid & 31;
    int gid = lane >> 2, tig = lane & 3;
    int m_warp = (wid >> 2) * 64;              // 0 or 64
    int n_warp = (wid & 3) * 32;               // 0,32,64,96

    int lrow = tid >> 3;                        // 0..31
    int kcol = (tid & 7) * 4;                   // 0..28

    int Keff = K;
    if (CAUSAL == 2) { int kc = m0 + 128; Keff = (kc < K) ? kc : K; }
    int iters = Keff >> 5;

    float acc[4][4][4];
#pragma unroll
    for (int a = 0; a < 4; a++)
#pragma unroll
        for (int b = 0; b < 4; b++)
#pragma unroll
            for (int cdx = 0; cdx < 4; cdx++) acc[a][b][cdx] = 0.f;

    const float* Ap = A + (long)(m0 + lrow) * lda + kcol;
    const float* Bp = B + (long)(n0 + lrow) * ldb + kcol;

    // ---- prologue: stage 0 ----
    {
        uint16_t* Ahi = sm16;
        uint16_t* Alo = Ahi + TILE_U16;
        uint16_t* Bhi = Alo + TILE_U16;
        uint16_t* Blo = Bhi + TILE_U16;
#pragma unroll
        for (int i = 0; i < 4; i++) {
            int row = lrow + 32 * i;
            float4 va = *(const float4*)(Ap + (long)(32 * i) * lda);
            float4 vb = *(const float4*)(Bp + (long)(32 * i) * ldb);
            unsigned short h0,l0,h1,l1,h2,l2,h3,l3;
            split2(va.x,h0,l0); split2(va.y,h1,l1); split2(va.z,h2,l2); split2(va.w,h3,l3);
            uint2 hp, lp;
            hp.x = (uint32_t)h0 | ((uint32_t)h1 << 16);
            hp.y = (uint32_t)h2 | ((uint32_t)h3 << 16);
            lp.x = (uint32_t)l0 | ((uint32_t)l1 << 16);
            lp.y = (uint32_t)l2 | ((uint32_t)l3 << 16);
            *(uint2*)(Ahi + row * TSTRIDE + kcol) = hp;
            *(uint2*)(Alo + row * TSTRIDE + kcol) = lp;
            split2(vb.x,h0,l0); split2(vb.y,h1,l1); split2(vb.z,h2,l2); split2(vb.w,h3,l3);
            hp.x = (uint32_t)h0 | ((uint32_t)h1 << 16);
            hp.y = (uint32_t)h2 | ((uint32_t)h3 << 16);
            lp.x = (uint32_t)l0 | ((uint32_t)l1 << 16);
            lp.y = (uint32_t)l2 | ((uint32_t)l3 << 16);
            *(uint2*)(Bhi + row * TSTRIDE + kcol) = hp;
            *(uint2*)(Blo + row * TSTRIDE + kcol) = lp;
        }
    }
    __syncthreads();

    for (int it = 0; it < iters; ++it) {
        int s = it & 1;
        uint16_t* Ahi = sm16 + s * STAGE_U16;
        uint16_t* Alo = Ahi + TILE_U16;
        uint16_t* Bhi = Alo + TILE_U16;
        uint16_t* Blo = Bhi + TILE_U16;

        // stage next tile into registers
        float4 rA[4], rB[4];
        bool more = (it + 1 < iters);
        if (more) {
            const float* An = Ap + (it + 1) * 32;
            const float* Bn = Bp + (it + 1) * 32;
#pragma unroll
            for (int i = 0; i < 4; i++) {
                rA[i] = *(const float4*)(An + (long)(32 * i) * lda);
                rB[i] = *(const float4*)(Bn + (long)(32 * i) * ldb);
            }
        }

        // ---- compute on stage s ----
#pragma unroll
        for (int ks = 0; ks < 2; ks++) {
            int k0 = ks * 16;
            int c0k = k0 + tig * 2;
            uint32_t ahi[4][4], alo[4][4], bhi[4][2], blo[4][2];
#pragma unroll
            for (int mi = 0; mi < 4; mi++) {
                int r0 = m_warp + mi * 16 + gid;
                ahi[mi][0] = lds32(Ahi, r0,     c0k);
                ahi[mi][1] = lds32(Ahi, r0 + 8, c0k);
                ahi[mi][2] = lds32(Ahi, r0,     c0k + 8);
                ahi[mi][3] = lds32(Ahi, r0 + 8, c0k + 8);
                alo[mi][0] = lds32(Alo, r0,     c0k);
                alo[mi][1] = lds32(Alo, r0 + 8, c0k);
                alo[mi][2] = lds32(Alo, r0,     c0k + 8);
                alo[mi][3] = lds32(Alo, r0 + 8, c0k + 8);
            }
#pragma unroll
            for (int ni = 0; ni < 4; ni++) {
                int rb = n_warp + ni * 8 + gid;
                bhi[ni][0] = lds32(Bhi, rb, c0k);
                bhi[ni][1] = lds32(Bhi, rb, c0k + 8);
                blo[ni][0] = lds32(Blo, rb, c0k);
                blo[ni][1] = lds32(Blo, rb, c0k + 8);
            }
#pragma unroll
            for (int mi = 0; mi < 4; mi++)
#pragma unroll
                for (int ni = 0; ni < 4; ni++) {
                    mma16816(acc[mi][ni], ahi[mi], bhi[ni]);
                    mma16816(acc[mi][ni], alo[mi], bhi[ni]);
                    mma16816(acc[mi][ni], ahi[mi], blo[ni]);
                }
        }

        // ---- store next tile to other stage ----
        if (more) {
            uint16_t* nAhi = sm16 + (s ^ 1) * STAGE_U16;
            uint16_t* nAlo = nAhi + TILE_U16;
            uint16_t* nBhi = nAlo + TILE_U16;
            uint16_t* nBlo = nBhi + TILE_U16;
#pragma unroll
            for (int i = 0; i < 4; i++) {
                int row = lrow + 32 * i;
                unsigned short h0,l0,h1,l1,h2,l2,h3,l3;
                split2(rA[i].x,h0,l0); split2(rA[i].y,h1,l1);
                split2(rA[i].z,h2,l2); split2(rA[i].w,h3,l3);
                uint2 hp, lp;
                hp.x = (uint32_t)h0 | ((uint32_t)h1 << 16);
                hp.y = (uint32_t)h2 | ((uint32_t)h3 << 16);
                lp.x = (uint32_t)l0 | ((uint32_t)l1 << 16);
                lp.y = (uint32_t)l2 | ((uint32_t)l3 << 16);
                *(uint2*)(nAhi + row * TSTRIDE + kcol) = hp;
                *(uint2*)(nAlo + row * TSTRIDE + kcol) = lp;
                split2(rB[i].x,h0,l0); split2(rB[i].y,h1,l1);
                split2(rB[i].z,h2,l2); split2(rB[i].w,h3,l3);
                hp.x = (uint32_t)h0 | ((uint32_t)h1 << 16);
                hp.y = (uint32_t)h2 | ((uint32_t)h3 << 16);
                lp.x = (uint32_t)l0 | ((uint32_t)l1 << 16);
                lp.y = (uint32_t)l2 | ((uint32_t)l3 << 16);
                *(uint2*)(nBhi + row * TSTRIDE + kcol) = hp;
                *(uint2*)(nBlo + row * TSTRIDE + kcol) = lp;
            }
        }
        __syncthreads();
    }

    // ---- epilogue ----
#pragma unroll
    for (int mi = 0; mi < 4; mi++) {
        long row = m0 + m_warp + mi * 16 + gid;
#pragma unroll
        for (int ni = 0; ni < 4; ni++) {
            int col = n0 + n_warp + ni * 8 + tig * 2;
            float b0 = 0.f, b1 = 0.f;
            if (bias) { b0 = bias[col]; b1 = bias[col + 1]; }
            float2 v0, v1;
            v0.x = acc[mi][ni][0] + b0;
            v0.y = acc[mi][ni][1] + b1;
            v1.x = acc[mi][ni][2] + b0;
            v1.y = acc[mi][ni][3] + b1;
            if (RELU) {
                v0.x = fmaxf(v0.x, 0.f); v0.y = fmaxf(v0.y, 0.f);
                v1.x = fmaxf(v1.x, 0.f); v1.y = fmaxf(v1.y, 0.f);
            }
            *(float2*)(C + row * ldc + col) = v0;
            *(float2*)(C + (row + 8) * ldc + col) = v1;
        }
    }
}

// ---------------------------------------------------------------------------
// Tiled fp32 transpose: in[z][R][C] -> out[z][C][R]
// ---------------------------------------------------------------------------
__global__ void transpose_kernel(const float* __restrict__ in,
                                 float* __restrict__ out, int R, int C) {
    __shared__ float t[32][33];
    long zo = (long)blockIdx.z * R * C;
    in += zo; out += zo;
    int c0 = blockIdx.x * 32, r0 = blockIdx.y * 32;
#pragma unroll
    for (int i = threadIdx.y; i < 32; i += 8)
        t[i][threadIdx.x] = in[(long)(r0 + i) * C + c0 + threadIdx.x];
    __syncthreads();
#pragma unroll
    for (int i = threadIdx.y; i < 32; i += 8)
        out[(long)(c0 + i) * R + r0 + threadIdx.x] = t[threadIdx.x][i];
}

// ---------------------------------------------------------------------------
// Embedding + positional encoding (float64 PE to match reference)
// ---------------------------------------------------------------------------
__global__ void embed_kernel(const int* __restrict__ x,
                             const float* __restrict__ emb,
                             float* __restrict__ out) {
    long idx = (long)blockIdx.x * blockDim.x + threadIdx.x;
    int d = (int)(idx & (DM - 1));
    int t = (int)(idx >> 10);
    int s = t & (SEQ - 1);
    int tok = x[t];
    int i = d >> 1;
    double ang = (double)s / pow(10000.0, (2.0 * (double)i) / (double)DM);
    double pe = (d & 1) ? cos(ang) : sin(ang);
    out[idx] = emb[(long)tok * DM + d] + (float)pe;
}

// ---------------------------------------------------------------------------
// Causal softmax (scale + mask fused); one block per row.
// ---------------------------------------------------------------------------
__global__ void softmax_kernel(float* __restrict__ P) {
    int row = blockIdx.x;
    int q = row & (SEQ - 1);
    float* p = P + (long)row * SEQ;
    int tid = threadIdx.x;
    int k0 = tid * 4;
    const float sc = 0.03125f;

    float4 v = *(const float4*)(p + k0);
    float a0 = (k0 + 0 <= q) ? v.x * sc : -1e9f;
    float a1 = (k0 + 1 <= q) ? v.y * sc : -1e9f;
    float a2 = (k0 + 2 <= q) ? v.z * sc : -1e9f;
    float a3 = (k0 + 3 <= q) ? v.w * sc : -1e9f;

    __shared__ float red[256];
    float mx = fmaxf(fmaxf(a0, a1), fmaxf(a2, a3));
    red[tid] = mx;
    __syncthreads();
    for (int o = 128; o > 0; o >>= 1) {
        if (tid < o) red[tid] = fmaxf(red[tid], red[tid + o]);
        __syncthreads();
    }
    mx = red[0];
    __syncthreads();

    float e0 = expf(a0 - mx), e1 = expf(a1 - mx);
    float e2 = expf(a2 - mx), e3 = expf(a3 - mx);
    red[tid] = e0 + e1 + e2 + e3;
    __syncthreads();
    for (int o = 128; o > 0; o >>= 1) {
        if (tid < o) red[tid] += red[tid + o];
        __syncthreads();
    }
    float inv = 1.f / red[0];
    float4 o4; o4.x = e0 * inv; o4.y = e1 * inv; o4.z = e2 * inv; o4.w = e3 * inv;
    *(float4*)(p + k0) = o4;
}

// ---------------------------------------------------------------------------
// Fused residual + LayerNorm
// ---------------------------------------------------------------------------
__global__ void ln_residual_kernel(const float* __restrict__ X,
                                   const float* __restrict__ Y,
                                   const float* __restrict__ g,
                                   const float* __restrict__ b,
                                   float* __restrict__ out) {
    int row = blockIdx.x;
    int tid = threadIdx.x;
    int c = tid * 4;
    float4 xv = *(const float4*)(X + (long)row * DM + c);
    float4 yv = *(const float4*)(Y + (long)row * DM + c);
    float v0 = xv.x + yv.x, v1 = xv.y + yv.y, v2 = xv.z + yv.z, v3 = xv.w + yv.w;

    __shared__ float red[256];
    red[tid] = v0 + v1 + v2 + v3;
    __syncthreads();
    for (int o = 128; o > 0; o >>= 1) {
        if (tid < o) red[tid] += red[tid + o];
        __syncthreads();
    }
    float mu = red[0] * (1.f / DM);
    __syncthreads();

    float d0 = v0 - mu, d1 = v1 - mu, d2 = v2 - mu, d3 = v3 - mu;
    red[tid] = d0 * d0 + d1 * d1 + d2 * d2 + d3 * d3;
    __syncthreads();
    for (int o = 128; o > 0; o >>= 1) {
        if (tid < o) red[tid] += red[tid + o];
        __syncthreads();
    }
    float inv = rsqrtf(red[0] * (1.f / DM) + 1e-5f);

    float4 gv = *(const float4*)(g + c);
    float4 bv = *(const float4*)(b + c);
    float4 o4;
    o4.x = d0 * inv * gv.x + bv.x;
    o4.y = d1 * inv * gv.y + bv.y;
    o4.z = d2 * inv * gv.z + bv.z;
    o4.w = d3 * inv * gv.w + bv.w;
    *(float4*)(out + (long)row * DM + c) = o4;
}

// ---------------------------------------------------------------------------
// Host driver
// ---------------------------------------------------------------------------
extern "C" void kernel_launch(void* const* d_in, const int* in_sizes, int n_in,
                              void* d_out, int out_size) {
    const int*   x    = (const int*)  d_in[0];
    const float* emb  = (const float*)d_in[1];
    const float* wq   = (const float*)d_in[2];
    const float* bq   = (const float*)d_in[3];
    const float* wk   = (const float*)d_in[4];
    const float* bk   = (const float*)d_in[5];
    const float* wv   = (const float*)d_in[6];
    const float* bv   = (const float*)d_in[7];
    const float* wr   = (const float*)d_in[8];
    const float* br   = (const float*)d_in[9];
    const float* ln1g = (const float*)d_in[10];
    const float* ln1b = (const float*)d_in[11];
    const float* w1   = (const float*)d_in[12];
    const float* b1   = (const float*)d_in[13];
    const float* w2   = (const float*)d_in[14];
    const float* b2   = (const float*)d_in[15];
    const float* ln2g = (const float*)d_in[16];
    const float* ln2b = (const float*)d_in[17];
    const float* wf   = (const float*)d_in[18];
    const float* bf   = (const float*)d_in[19];
    float* out = (float*)d_out;

    float *ph, *pQ, *pK, *pV, *pVt, *pP, *pO, *pa, *pf, *pm;
    float *wqT, *wkT, *wvT, *wrT, *w1T, *w2T, *wfT;
    cudaGetSymbolAddress((void**)&ph,  g_h);
    cudaGetSymbolAddress((void**)&pQ,  g_Q);
    cudaGetSymbolAddress((void**)&pK,  g_Kb);
    cudaGetSymbolAddress((void**)&pV,  g_Vb);
    cudaGetSymbolAddress((void**)&pVt, g_Vt);
    cudaGetSymbolAddress((void**)&pP,  g_P);
    cudaGetSymbolAddress((void**)&pO,  g_O);
    cudaGetSymbolAddress((void**)&pa,  g_a);
    cudaGetSymbolAddress((void**)&pf,  g_ffin);
    cudaGetSymbolAddress((void**)&pm,  g_mid);
    cudaGetSymbolAddress((void**)&wqT, g_wqT);
    cudaGetSymbolAddress((void**)&wkT, g_wkT);
    cudaGetSymbolAddress((void**)&wvT, g_wvT);
    cudaGetSymbolAddress((void**)&wrT, g_wrT);
    cudaGetSymbolAddress((void**)&w1T, g_w1T);
    cudaGetSymbolAddress((void**)&w2T, g_w2T);
    cudaGetSymbolAddress((void**)&wfT, g_wfT);

    cudaFuncSetAttribute(hgemm<0, false>, cudaFuncAttributeMaxDynamicSharedMemorySize, GSMEM_BYTES);
    cudaFuncSetAttribute(hgemm<0, true>,  cudaFuncAttributeMaxDynamicSharedMemorySize, GSMEM_BYTES);
    cudaFuncSetAttribute(hgemm<1, false>, cudaFuncAttributeMaxDynamicSharedMemorySize, GSMEM_BYTES);
    cudaFuncSetAttribute(hgemm<2, false>, cudaFuncAttributeMaxDynamicSharedMemorySize, GSMEM_BYTES);

    dim3 tb(32, 8);
    // Weight transposes (once per launch)
    transpose_kernel<<<dim3(32, 32, NLAY * NH), tb>>>(wq, wqT, DM, DM);
    transpose_kernel<<<dim3(32, 32, NLAY * NH), tb>>>(wk, wkT, DM, DM);
    transpose_kernel<<<dim3(32, 32, NLAY * NH), tb>>>(wv, wvT, DM, DM);
    transpose_kernel<<<dim3(32, 256, NLAY), tb>>>(wr, wrT, NH * DM, DM);
    transpose_kernel<<<dim3(128, 32, NLAY), tb>>>(w1, w1T, DM, 4 * DM);
    transpose_kernel<<<dim3(32, 128, NLAY), tb>>>(w2, w2T, 4 * DM, DM);
    transpose_kernel<<<dim3(VOC / 32, 32, 1), tb>>>(wf, wfT, DM, VOC);

    embed_kernel<<<(TOK * DM) / 256, 256>>>(x, emb, ph);

    for (int l = 0; l < NLAY; l++) {
        const float* wqTl = wqT + (long)l * NH * DM * DM;
        const float* wkTl = wkT + (long)l * NH * DM * DM;
        const float* wvTl = wvT + (long)l * NH * DM * DM;
        const float* wrTl = wrT + (long)l * NH * DM * DM;
        const float* w1Tl = w1T + (long)l * 4 * DM * DM;
        const float* w2Tl = w2T + (long)l * 4 * DM * DM;
        const float* bql = bq + (long)l * NH * DM;
        const float* bkl = bk + (long)l * NH * DM;
        const float* bvl = bv + (long)l * NH * DM;
        const float* brl = br + (long)l * DM;
        const float* b1l = b1 + (long)l * 4 * DM;
        const float* b2l = b2 + (long)l * DM;

        // QKV projections (z = head)
        dim3 gqkv(DM / 128, TOK / 128, NH);
        hgemm<0, false><<<gqkv, 256, GSMEM_BYTES>>>(ph, wqTl, bql, pQ,
            DM, DM, DM, DM,
            0, 0, BIG,  0, (long)DM * DM, BIG,  0, (long)TOK * DM, BIG,  0, DM, BIG);
        hgemm<0, false><<<gqkv, 256, GSMEM_BYTES>>>(ph, wkTl, bkl, pK,
            DM, DM, DM, DM,
            0, 0, BIG,  0, (long)DM * DM, BIG,  0, (long)TOK * DM, BIG,  0, DM, BIG);
        hgemm<0, false><<<gqkv, 256, GSMEM_BYTES>>>(ph, wvTl, bvl, pV,
            DM, DM, DM, DM,
            0, 0, BIG,  0, (long)DM * DM, BIG,  0, (long)TOK * DM, BIG,  0, DM, BIG);

        // V transpose per (h,b) slice: [s][e] -> [e][s]
        transpose_kernel<<<dim3(32, 32, NH * BB), tb>>>(pV, pVt, SEQ, DM);

        // scores = Q @ K^T (z = h*4+b); skip fully-masked tiles
        dim3 gsc(SEQ / 128, SEQ / 128, NH * BB);
        hgemm<1, false><<<gsc, 256, GSMEM_BYTES>>>(pQ, pK, nullptr, pP,
            DM, DM, DM, SEQ,
            0, (long)SEQ * DM, BIG,  0, (long)SEQ * DM, BIG,
            0, (long)SEQ * SEQ, BIG,  0, 0, BIG);

        softmax_kernel<<<NH * BB * SEQ, 256>>>(pP);

        // O = P @ V (B = V^T), K clamped to diagonal, concat-head C layout
        dim3 gpv(DM / 128, SEQ / 128, NH * BB);
        hgemm<2, false><<<gpv, 256, GSMEM_BYTES>>>(pP, pVt, nullptr, pO,
            SEQ, SEQ, SEQ, NH * DM,
            0, (long)SEQ * SEQ, BIG,  0, (long)DM * SEQ, BIG,
            (long)DM, (long)SEQ * NH * DM, BB,  0, 0, BIG);

        // reducing layer
        dim3 gwr(DM / 128, TOK / 128, 1);
        hgemm<0, false><<<gwr, 256, GSMEM_BYTES>>>(pO, wrTl, brl, pa,
            NH * DM, NH * DM, NH * DM, DM,
            0, 0, BIG,  0, 0, BIG,  0, 0, BIG,  0, 0, BIG);

        ln_residual_kernel<<<TOK, 256>>>(pa, ph, ln1g + (long)l * DM,
                                         ln1b + (long)l * DM, pf);

        dim3 gf1((4 * DM) / 128, TOK / 128, 1);
        hgemm<0, true><<<gf1, 256, GSMEM_BYTES>>>(pf, w1Tl, b1l, pm,
            DM, DM, DM, 4 * DM,
            0, 0, BIG,  0, 0, BIG,  0, 0, BIG,  0, 0, BIG);

        dim3 gf2(DM / 128, TOK / 128, 1);
        hgemm<0, false><<<gf2, 256, GSMEM_BYTES>>>(pm, w2Tl, b2l, pa,
            4 * DM, 4 * DM, 4 * DM, DM,
            0, 0, BIG,  0, 0, BIG,  0, 0, BIG,  0, 0, BIG);

        ln_residual_kernel<<<TOK, 256>>>(pa, pf, ln2g + (long)l * DM,
                                         ln2b + (long)l * DM, ph);
    }

    // logits = h @ wf + bf
    dim3 gfin(VOC / 128, TOK / 128, 1);
    hgemm<0, false><<<gfin, 256, GSMEM_BYTES>>>(ph, wfT, bf, out,
        DM, DM, DM, VOC,
        0, 0, BIG,  0, 0, BIG,  0, 0, BIG,  0, 0, BIG);
}